// round 1
// baseline (speedup 1.0000x reference)
#include <cuda_runtime.h>
#include <math.h>

#define NN 8192
#define DD 128
#define NCENT 64
#define NCLS 7
#define NLAYER 4
#define KSPLIT 4

#define MINN 1e-15f
#define EPSF 1e-5f
#define MAXNRM (1.0f - 1e-5f)

// ---------------- scratch (static device memory; no allocs) ----------------
static __device__ float g_h[NN * DD];
static __device__ float g_res[NN * DD];
static __device__ float g_log[NN * DD];
static __device__ float g_part[KSPLIT][NN * DD];
static __device__ float g_hypb[NLAYER * DD];
static __device__ float g_Wt[NLAYER * DD * DD];
static __device__ float g_dsum[NCENT];
static __device__ float g_z[NN * NCLS];

// ---------------- helpers ----------------
__device__ __forceinline__ float wsum(float v) {
    v += __shfl_xor_sync(0xffffffffu, v, 16);
    v += __shfl_xor_sync(0xffffffffu, v, 8);
    v += __shfl_xor_sync(0xffffffffu, v, 4);
    v += __shfl_xor_sync(0xffffffffu, v, 2);
    v += __shfl_xor_sync(0xffffffffu, v, 1);
    return v;
}

__device__ __forceinline__ float artanhf_(float x) {
    x = fminf(fmaxf(x, -1.0f + EPSF), 1.0f - EPSF);
    return 0.5f * (log1pf(x) - log1pf(-x));
}

// clamped row norm over 128 elements held as v[4] per lane (lane-major)
__device__ __forceinline__ float rnorm4(const float v[4]) {
    float s = v[0] * v[0] + v[1] * v[1] + v[2] * v[2] + v[3] * v[3];
    s = wsum(s);
    return fmaxf(sqrtf(s), MINN);
}

__device__ __forceinline__ void proj4(float v[4]) {
    float n = rnorm4(v);
    if (n > MAXNRM) {
        float s = MAXNRM / n;
        v[0] *= s; v[1] *= s; v[2] *= s; v[3] *= s;
    }
}

__device__ __forceinline__ void expmap04(float v[4]) {
    float n = rnorm4(v);
    float s = tanhf(n) / n;
    v[0] *= s; v[1] *= s; v[2] *= s; v[3] *= s;
}

__device__ __forceinline__ void logmap04(float v[4]) {
    float n = rnorm4(v);
    float s = artanhf_(n) / n;
    v[0] *= s; v[1] *= s; v[2] *= s; v[3] *= s;
}

// ---------------- kernels ----------------

// h = proj(expmap0(x)); res = h
__global__ void k_in(const float* __restrict__ x) {
    int w = (blockIdx.x * blockDim.x + threadIdx.x) >> 5;
    int lane = threadIdx.x & 31;
    if (w >= NN) return;
    const float* r = x + w * DD + lane;
    float v[4];
#pragma unroll
    for (int i = 0; i < 4; i++) v[i] = r[i * 32];
    expmap04(v);
    proj4(v);
    float* o = g_h + w * DD + lane;
    float* o2 = g_res + w * DD + lane;
#pragma unroll
    for (int i = 0; i < 4; i++) { o[i * 32] = v[i]; o2[i * 32] = v[i]; }
}

// hyp_b[l] = proj(expmap0(b_conv[l]))  -- 4 warps, one per layer
__global__ void k_hypb(const float* __restrict__ b) {
    int l = threadIdx.x >> 5;
    int lane = threadIdx.x & 31;
    float v[4];
#pragma unroll
    for (int i = 0; i < 4; i++) v[i] = b[l * DD + lane + i * 32];
    expmap04(v);
    proj4(v);
#pragma unroll
    for (int i = 0; i < 4; i++) g_hypb[l * DD + lane + i * 32] = v[i];
}

// Wt[l][k][j] = W[l][j][k]
__global__ void k_transW(const float* __restrict__ W) {
    int l = blockIdx.x;
    const float* Wl = W + l * DD * DD;
    float* T = g_Wt + l * DD * DD;
    for (int idx = threadIdx.x; idx < DD * DD; idx += blockDim.x) {
        T[(idx & 127) * DD + (idx >> 7)] = Wl[idx];
    }
}

// C_part[blockIdx.y] = A[M,K-chunk] @ B[K,128] ; 64x128 tile, 8x8 micro, 128 thr
__global__ void k_gemm(const float* __restrict__ A, const float* __restrict__ B,
                       int M, int K) {
    __shared__ float As[8][65];
    __shared__ float Bs[8][128];
    const int tid = threadIdx.x;
    const int m0 = blockIdx.x * 64;
    const int kchunk = K / KSPLIT;
    const int kb = blockIdx.y * kchunk;

    float acc[8][8];
#pragma unroll
    for (int i = 0; i < 8; i++)
#pragma unroll
        for (int j = 0; j < 8; j++) acc[i][j] = 0.0f;

    const int rb = (tid >> 4) << 3;   // row base 0..56
    const int cb = (tid & 15) << 3;   // col base 0..120

    for (int k0 = kb; k0 < kb + kchunk; k0 += 8) {
#pragma unroll
        for (int i = 0; i < 4; i++) {
            int idx = tid + (i << 7);
            int m = idx >> 3, kk = idx & 7;
            As[kk][m] = A[(size_t)(m0 + m) * K + (k0 + kk)];
        }
#pragma unroll
        for (int i = 0; i < 8; i++) {
            int idx = tid + (i << 7);
            int kk = idx >> 7, n = idx & 127;
            Bs[kk][n] = B[(size_t)(k0 + kk) * DD + n];
        }
        __syncthreads();
#pragma unroll
        for (int kk = 0; kk < 8; kk++) {
            float a[8], bb[8];
#pragma unroll
            for (int i = 0; i < 8; i++) a[i] = As[kk][rb + i];
#pragma unroll
            for (int j = 0; j < 8; j++) bb[j] = Bs[kk][cb + j];
#pragma unroll
            for (int i = 0; i < 8; i++)
#pragma unroll
                for (int j = 0; j < 8; j++)
                    acc[i][j] = fmaf(a[i], bb[j], acc[i][j]);
        }
        __syncthreads();
    }
    float* Cp = g_part[blockIdx.y];
#pragma unroll
    for (int i = 0; i < 8; i++) {
#pragma unroll
        for (int j = 0; j < 8; j += 4) {
            float4 v4 = make_float4(acc[i][j], acc[i][j + 1], acc[i][j + 2], acc[i][j + 3]);
            *(float4*)&Cp[(size_t)(m0 + rb + i) * DD + cb + j] = v4;
        }
    }
}

// mobius_matvec scale + proj + mobius_add(hyp_b) + proj + logmap0 -> g_log
__global__ void k_post_linear(int l) {
    int w = (blockIdx.x * blockDim.x + threadIdx.x) >> 5;
    int lane = threadIdx.x & 31;
    if (w >= NN) return;
    int o = w * DD + lane;
    float mv[4], hx[4], y[4];
#pragma unroll
    for (int i = 0; i < 4; i++) {
        int oo = o + i * 32;
        mv[i] = g_part[0][oo] + g_part[1][oo] + g_part[2][oo] + g_part[3][oo];
        hx[i] = g_h[oo];
        y[i] = g_hypb[l * DD + lane + i * 32];
    }
    float xn = rnorm4(hx);
    float mxn = rnorm4(mv);
    float s = tanhf(mxn / xn * artanhf_(xn)) / mxn;
#pragma unroll
    for (int i = 0; i < 4; i++) mv[i] *= s;
    proj4(mv);
    // mobius_add(mv, y)
    float x2 = wsum(mv[0] * mv[0] + mv[1] * mv[1] + mv[2] * mv[2] + mv[3] * mv[3]);
    float y2 = wsum(y[0] * y[0] + y[1] * y[1] + y[2] * y[2] + y[3] * y[3]);
    float xy = wsum(mv[0] * y[0] + mv[1] * y[1] + mv[2] * y[2] + mv[3] * y[3]);
    float ca = 1.0f + 2.0f * xy + y2;
    float cbf = 1.0f - x2;
    float den = fmaxf(1.0f + 2.0f * xy + x2 * y2, MINN);
#pragma unroll
    for (int i = 0; i < 4; i++) mv[i] = (ca * mv[i] + cbf * y[i]) / den;
    proj4(mv);
    logmap04(mv);
#pragma unroll
    for (int i = 0; i < 4; i++) g_log[o + i * 32] = mv[i];
}

// agg -> proj(expmap0) -> relu in tangent -> proj(expmap0) ; optional residual
__global__ void k_post_agg(int add_res, int save_res) {
    int w = (blockIdx.x * blockDim.x + threadIdx.x) >> 5;
    int lane = threadIdx.x & 31;
    if (w >= NN) return;
    int o = w * DD + lane;
    float v[4];
#pragma unroll
    for (int i = 0; i < 4; i++) {
        int oo = o + i * 32;
        v[i] = g_part[0][oo] + g_part[1][oo] + g_part[2][oo] + g_part[3][oo];
    }
    expmap04(v); proj4(v);
    logmap04(v);
#pragma unroll
    for (int i = 0; i < 4; i++) v[i] = fmaxf(v[i], 0.0f);
    expmap04(v); proj4(v);
    if (add_res) {
#pragma unroll
        for (int i = 0; i < 4; i++) v[i] += g_res[o + i * 32];
    }
#pragma unroll
    for (int i = 0; i < 4; i++) g_h[o + i * 32] = v[i];
    if (save_res) {
#pragma unroll
        for (int i = 0; i < 4; i++) g_res[o + i * 32] = v[i];
    }
}

__global__ void k_logmap() {
    int w = (blockIdx.x * blockDim.x + threadIdx.x) >> 5;
    int lane = threadIdx.x & 31;
    if (w >= NN) return;
    int o = w * DD + lane;
    float v[4];
#pragma unroll
    for (int i = 0; i < 4; i++) v[i] = g_h[o + i * 32];
    logmap04(v);
#pragma unroll
    for (int i = 0; i < 4; i++) g_log[o + i * 32] = v[i];
}

__global__ void k_zero() {
    if (threadIdx.x < NCENT) g_dsum[threadIdx.x] = 0.0f;
}

// accumulate sum over nodes of poincare_dist(h[n], centroid[c]) into g_dsum[c]
__global__ void k_cent(const float* __restrict__ cent) {
    __shared__ float sC[NCENT * 129];
    __shared__ float hs[4][DD];
    int tx = threadIdx.x;  // centroid 0..63
    int ty = threadIdx.y;  // node slot 0..3
    int tid = ty * 64 + tx;
    for (int idx = tid; idx < NCENT * DD; idx += 256)
        sC[(idx >> 7) * 129 + (idx & 127)] = cent[idx];
    int n = (blockIdx.x << 2) + ty;
    const float* hr = g_h + (size_t)n * DD;
    hs[ty][tx] = hr[tx];
    hs[ty][tx + 64] = hr[tx + 64];
    __syncthreads();
    const float* cr = sC + tx * 129;
    float x2 = 0.f, xy = 0.f, y2 = 0.f;
#pragma unroll 4
    for (int k = 0; k < DD; k++) {
        float a = hs[ty][k];
        float b = cr[k];
        x2 += a * a; xy += a * b; y2 += b * b;
    }
    // mobius_add(-x, y): num = (1-2xy+y2)(-x) + (1-x2) y ; den = 1-2xy+x2*y2
    float A = 1.0f - 2.0f * xy + y2;
    float Bc = 1.0f - x2;
    float nn = 0.f;
#pragma unroll 4
    for (int k = 0; k < DD; k++) {
        float t = Bc * cr[k] - A * hs[ty][k];
        nn += t * t;
    }
    float den = fmaxf(1.0f - 2.0f * xy + x2 * y2, MINN);
    float d = fmaxf(sqrtf(nn) / den, MINN);
    atomicAdd(&g_dsum[tx], 2.0f * artanhf_(d));
}

// z[n][cls] = logmap0(h)[n] . W_mlp1[cls] + b_mlp1[cls]
__global__ void k_z(const float* __restrict__ W1, const float* __restrict__ b1) {
    int w = (blockIdx.x * blockDim.x + threadIdx.x) >> 5;
    int lane = threadIdx.x & 31;
    if (w >= NN) return;
    int o = w * DD + lane;
    float v[4];
#pragma unroll
    for (int i = 0; i < 4; i++) v[i] = g_log[o + i * 32];
#pragma unroll
    for (int cls = 0; cls < NCLS; cls++) {
        float p = 0.f;
#pragma unroll
        for (int i = 0; i < 4; i++) p += v[i] * W1[cls * DD + lane + i * 32];
        p = wsum(p);
        if (lane == 0) g_z[w * NCLS + cls] = p + b1[cls];
    }
}

// softmax over the node axis per class
__global__ void k_softmax(float* __restrict__ out) {
    int cls = blockIdx.x;
    int t = threadIdx.x;
    __shared__ float sh[256];
    float m = -1e30f;
    for (int n = t; n < NN; n += 256) m = fmaxf(m, g_z[n * NCLS + cls]);
    sh[t] = m; __syncthreads();
    for (int s = 128; s; s >>= 1) { if (t < s) sh[t] = fmaxf(sh[t], sh[t + s]); __syncthreads(); }
    m = sh[0]; __syncthreads();
    float ss = 0.f;
    for (int n = t; n < NN; n += 256) ss += expf(g_z[n * NCLS + cls] - m);
    sh[t] = ss; __syncthreads();
    for (int s = 128; s; s >>= 1) { if (t < s) sh[t] += sh[t + s]; __syncthreads(); }
    float inv = 1.0f / sh[0];
    for (int n = t; n < NN; n += 256)
        out[7 + n * NCLS + cls] = expf(g_z[n * NCLS + cls] - m) * inv;
}

// readout mean -> logmap0 -> h_r ; logits (softmax over size-1 axis) = ones
__global__ void k_final(float* __restrict__ out, int hr_off) {
    int t = threadIdx.x;  // 64
    __shared__ float sh[64];
    float r = g_dsum[t] * (1.0f / (float)NN);
    sh[t] = r * r;
    __syncthreads();
    if (t == 0) {
        float s = 0.f;
        for (int i = 0; i < 64; i++) s += sh[i];
        sh[0] = s;
    }
    __syncthreads();
    float nrm = fmaxf(sqrtf(sh[0]), MINN);
    float s2 = artanhf_(nrm) / nrm;
    out[hr_off + t] = r * s2;
    if (t < NCLS) out[t] = 1.0f;
}

// ---------------- launch ----------------
extern "C" void kernel_launch(void* const* d_in, const int* in_sizes, int n_in,
                              void* d_out, int out_size) {
    const float* x = (const float*)d_in[0];
    const float* adj = (const float*)d_in[1];
    // d_in[2] = graph_indicator (unused)
    const float* W_conv = (const float*)d_in[3];
    const float* b_conv = (const float*)d_in[4];
    const float* cent = (const float*)d_in[5];
    // d_in[6] = W_mlp, d_in[7] = b_mlp (unused: softmax over size-1 axis == 1)
    const float* W1 = (const float*)d_in[8];
    const float* b1 = (const float*)d_in[9];
    float* out = (float*)d_out;

    float *p_h = 0, *p_log = 0, *p_Wt = 0;
    cudaGetSymbolAddress((void**)&p_h, g_h);
    cudaGetSymbolAddress((void**)&p_log, g_log);
    cudaGetSymbolAddress((void**)&p_Wt, g_Wt);

    k_in<<<NN / 8, 256>>>(x);
    k_hypb<<<1, 128>>>(b_conv);
    k_transW<<<4, 256>>>(W_conv);

    dim3 gg(NN / 64, KSPLIT);
    for (int l = 0; l < NLAYER; l++) {
        k_gemm<<<gg, 128>>>(p_h, p_Wt + l * DD * DD, NN, DD);
        k_post_linear<<<NN / 8, 256>>>(l);
        k_gemm<<<gg, 128>>>(adj, p_log, NN, NN);
        int ar = (l == 1 || l == 3) ? 1 : 0;
        int sr = (l == 1) ? 1 : 0;
        k_post_agg<<<NN / 8, 256>>>(ar, sr);
    }
    k_logmap<<<NN / 8, 256>>>();
    k_zero<<<1, 64>>>();
    k_cent<<<NN / 4, dim3(64, 4)>>>(cent);
    k_z<<<NN / 8, 256>>>(W1, b1);
    k_softmax<<<NCLS, 256>>>(out);
    k_final<<<1, 64>>>(out, out_size - NCENT);
}

// round 3
// speedup vs baseline: 2.2073x; 2.2073x over previous
#include <cuda_runtime.h>
#include <math.h>
#include <stdint.h>

#define NN 8192
#define DD 128
#define NCENT 64
#define NCLS 7
#define NLAYER 4

#define MINN 1e-15f
#define EPSF 1e-5f
#define MAXNRM (1.0f - 1e-5f)

#define BM 128
#define BK 32
#define SMEMSZ (2 * 8192 * 4)  // 2 stages * (4096 A + 4096 B) floats

// ---------------- scratch ----------------
static __device__ float g_h[NN * DD];
static __device__ float g_res[NN * DD];
static __device__ float g_log[NN * DD];
static __device__ float g_logT[DD * NN];
static __device__ float g_part[2][NN * DD];
static __device__ float g_hypb[NLAYER * DD];
static __device__ float g_dsum[NCENT];
static __device__ float g_z[NN * NCLS];

// ---------------- helpers ----------------
__device__ __forceinline__ float wsum(float v) {
    v += __shfl_xor_sync(0xffffffffu, v, 16);
    v += __shfl_xor_sync(0xffffffffu, v, 8);
    v += __shfl_xor_sync(0xffffffffu, v, 4);
    v += __shfl_xor_sync(0xffffffffu, v, 2);
    v += __shfl_xor_sync(0xffffffffu, v, 1);
    return v;
}

__device__ __forceinline__ float artanhf_(float x) {
    x = fminf(fmaxf(x, -1.0f + EPSF), 1.0f - EPSF);
    return 0.5f * (log1pf(x) - log1pf(-x));
}

__device__ __forceinline__ float rnorm4(const float v[4]) {
    float s = v[0] * v[0] + v[1] * v[1] + v[2] * v[2] + v[3] * v[3];
    s = wsum(s);
    return fmaxf(sqrtf(s), MINN);
}

__device__ __forceinline__ void proj4(float v[4]) {
    float n = rnorm4(v);
    if (n > MAXNRM) {
        float s = MAXNRM / n;
        v[0] *= s; v[1] *= s; v[2] *= s; v[3] *= s;
    }
}

__device__ __forceinline__ void expmap04(float v[4]) {
    float n = rnorm4(v);
    float s = tanhf(n) / n;
    v[0] *= s; v[1] *= s; v[2] *= s; v[3] *= s;
}

__device__ __forceinline__ void logmap04(float v[4]) {
    float n = rnorm4(v);
    float s = artanhf_(n) / n;
    v[0] *= s; v[1] *= s; v[2] *= s; v[3] *= s;
}

__device__ __forceinline__ float rnaf(float x) {
    uint32_t r;
    asm("cvt.rna.tf32.f32 %0, %1;" : "=r"(r) : "f"(x));
    return __uint_as_float(r);
}
__device__ __forceinline__ uint32_t fu(float x) { return __float_as_uint(x); }

__device__ __forceinline__ void mma8(float c[4], uint32_t a0, uint32_t a1,
                                     uint32_t a2, uint32_t a3,
                                     uint32_t b0, uint32_t b1) {
    asm volatile(
        "mma.sync.aligned.m16n8k8.row.col.f32.tf32.tf32.f32 "
        "{%0,%1,%2,%3},{%4,%5,%6,%7},{%8,%9},{%0,%1,%2,%3};"
        : "+f"(c[0]), "+f"(c[1]), "+f"(c[2]), "+f"(c[3])
        : "r"(a0), "r"(a1), "r"(a2), "r"(a3), "r"(b0), "r"(b1));
}

// ---------------- tf32 tensor-core GEMM ----------------
// C[(m0..m0+127)][0..127] = A[m,kbase..] @ B^T  (Bt is [128 n-rows][K]).
// Permuted SMEM layout: (r,k) -> word r*32 + ((k&3)^(r&3))*8 + ((k>>2)^(4*(r&1)))
__global__ void __launch_bounds__(256, 1)
k_tgemm(const float* __restrict__ A, const float* __restrict__ Bt,
        long lda, long ldb, int iters, float* __restrict__ Cbase) {
    extern __shared__ float sm[];
    const int tid = threadIdx.x;
    const int m0 = blockIdx.x * BM;
    const long kbase = (long)blockIdx.y * iters * BK;
    float* Cout = Cbase + (size_t)blockIdx.y * NN * DD;

    // ---- store-side precompute (4 float4 per thread for A and for B) ----
    const float* ag[4];
    const float* bg[4];
    int stw[4], srx[4];
#pragma unroll
    for (int p = 0; p < 4; p++) {
        int i = tid + p * 256;
        int r = i >> 3, q = i & 7;
        ag[p] = A + (size_t)(m0 + r) * lda + kbase + q * 4;
        bg[p] = Bt + (size_t)r * ldb + kbase + q * 4;
        stw[p] = r * 32 + (q ^ ((r & 1) << 2));
        srx[p] = r & 3;
    }

    // ---- compute-side precompute ----
    const int w = tid >> 5, lane = tid & 31;
    const int c = lane & 3, rr = lane >> 2;
    const int m0w = (w & 3) * 32, n0w = (w >> 2) * 64;
    const int ra0 = m0w + rr;
    const int aoff = ra0 * 32 + ((c ^ (ra0 & 3)) << 3);
    const int apar = (ra0 & 1) << 2;
    const int nrow = n0w + rr;
    const int boff = nrow * 32 + ((c ^ (nrow & 3)) << 3);
    const int bpar = (nrow & 1) << 2;

    float acc[2][8][4];
#pragma unroll
    for (int mt = 0; mt < 2; mt++)
#pragma unroll
        for (int nt = 0; nt < 8; nt++)
#pragma unroll
            for (int e = 0; e < 4; e++) acc[mt][nt][e] = 0.0f;

    float4 ra[4], rb[4];
#pragma unroll
    for (int p = 0; p < 4; p++) {
        ra[p] = *(const float4*)ag[p];
        rb[p] = *(const float4*)bg[p];
    }
    // STS stage 0
    {
        float* sA = sm;
        float* sB = sm + 4096;
#pragma unroll
        for (int p = 0; p < 4; p++) {
            int b0w = stw[p], rx = srx[p];
            sA[b0w + ((0 ^ rx) << 3)] = rnaf(ra[p].x);
            sA[b0w + ((1 ^ rx) << 3)] = rnaf(ra[p].y);
            sA[b0w + ((2 ^ rx) << 3)] = rnaf(ra[p].z);
            sA[b0w + ((3 ^ rx) << 3)] = rnaf(ra[p].w);
            sB[b0w + ((0 ^ rx) << 3)] = rnaf(rb[p].x);
            sB[b0w + ((1 ^ rx) << 3)] = rnaf(rb[p].y);
            sB[b0w + ((2 ^ rx) << 3)] = rnaf(rb[p].z);
            sB[b0w + ((3 ^ rx) << 3)] = rnaf(rb[p].w);
        }
    }
    __syncthreads();

    for (int i = 0; i < iters; i++) {
        const int cur = i & 1;
        const bool more = (i + 1 < iters);
        if (more) {
#pragma unroll
            for (int p = 0; p < 4; p++) {
                ra[p] = *(const float4*)(ag[p] + (size_t)(i + 1) * BK);
                rb[p] = *(const float4*)(bg[p] + (size_t)(i + 1) * BK);
            }
        }
        // ---- compute on stage cur ----
        {
            const float* sA = sm + cur * 8192;
            const float* sB = sA + 4096;
#pragma unroll
            for (int h = 0; h < 2; h++) {
                float4 Af[2][2];
#pragma unroll
                for (int mt = 0; mt < 2; mt++) {
                    int base = aoff + mt * 512 + (apar ^ (h << 2));
                    Af[mt][0] = *(const float4*)(sA + base);
                    Af[mt][1] = *(const float4*)(sA + base + 256);
                }
                float4 Bf[8];
#pragma unroll
                for (int nt = 0; nt < 8; nt++)
                    Bf[nt] = *(const float4*)(sB + boff + nt * 256 + (bpar ^ (h << 2)));
#pragma unroll
                for (int t = 0; t < 2; t++) {
#pragma unroll
                    for (int mt = 0; mt < 2; mt++) {
                        uint32_t a0 = fu(t ? Af[mt][0].z : Af[mt][0].x);
                        uint32_t a2 = fu(t ? Af[mt][0].w : Af[mt][0].y);
                        uint32_t a1 = fu(t ? Af[mt][1].z : Af[mt][1].x);
                        uint32_t a3 = fu(t ? Af[mt][1].w : Af[mt][1].y);
#pragma unroll
                        for (int nt = 0; nt < 8; nt++) {
                            uint32_t b0 = fu(t ? Bf[nt].z : Bf[nt].x);
                            uint32_t b1 = fu(t ? Bf[nt].w : Bf[nt].y);
                            mma8(acc[mt][nt], a0, a1, a2, a3, b0, b1);
                        }
                    }
                }
            }
        }
        if (more) {
            float* sA = sm + (cur ^ 1) * 8192;
            float* sB = sA + 4096;
#pragma unroll
            for (int p = 0; p < 4; p++) {
                int b0w = stw[p], rx = srx[p];
                sA[b0w + ((0 ^ rx) << 3)] = rnaf(ra[p].x);
                sA[b0w + ((1 ^ rx) << 3)] = rnaf(ra[p].y);
                sA[b0w + ((2 ^ rx) << 3)] = rnaf(ra[p].z);
                sA[b0w + ((3 ^ rx) << 3)] = rnaf(ra[p].w);
                sB[b0w + ((0 ^ rx) << 3)] = rnaf(rb[p].x);
                sB[b0w + ((1 ^ rx) << 3)] = rnaf(rb[p].y);
                sB[b0w + ((2 ^ rx) << 3)] = rnaf(rb[p].z);
                sB[b0w + ((3 ^ rx) << 3)] = rnaf(rb[p].w);
            }
            __syncthreads();
        }
    }
    // ---- epilogue ----
#pragma unroll
    for (int mt = 0; mt < 2; mt++) {
        int row = m0 + m0w + mt * 16 + rr;
#pragma unroll
        for (int nt = 0; nt < 8; nt++) {
            int col = n0w + nt * 8 + 2 * c;
            *(float2*)&Cout[(size_t)row * DD + col] =
                make_float2(acc[mt][nt][0], acc[mt][nt][1]);
            *(float2*)&Cout[(size_t)(row + 8) * DD + col] =
                make_float2(acc[mt][nt][2], acc[mt][nt][3]);
        }
    }
}

// ---------------- data-prep ----------------
__global__ void k_transpose() {
    __shared__ float t[32][33];
    int bx = blockIdx.x, by = blockIdx.y;
    int x = threadIdx.x, y = threadIdx.y;
#pragma unroll
    for (int r = 0; r < 32; r += 8)
        t[y + r][x] = g_log[(size_t)(bx * 32 + y + r) * DD + by * 32 + x];
    __syncthreads();
#pragma unroll
    for (int r = 0; r < 32; r += 8)
        g_logT[(size_t)(by * 32 + y + r) * NN + bx * 32 + x] = t[x][y + r];
}

// ---------------- pointwise ----------------
__global__ void k_in(const float* __restrict__ x) {
    int w = (blockIdx.x * blockDim.x + threadIdx.x) >> 5;
    int lane = threadIdx.x & 31;
    if (w >= NN) return;
    const float* r = x + w * DD + lane;
    float v[4];
#pragma unroll
    for (int i = 0; i < 4; i++) v[i] = r[i * 32];
    expmap04(v);
    proj4(v);
    float* o = g_h + w * DD + lane;
    float* o2 = g_res + w * DD + lane;
#pragma unroll
    for (int i = 0; i < 4; i++) { o[i * 32] = v[i]; o2[i * 32] = v[i]; }
}

__global__ void k_hypb(const float* __restrict__ b) {
    int l = threadIdx.x >> 5;
    int lane = threadIdx.x & 31;
    float v[4];
#pragma unroll
    for (int i = 0; i < 4; i++) v[i] = b[l * DD + lane + i * 32];
    expmap04(v);
    proj4(v);
#pragma unroll
    for (int i = 0; i < 4; i++) g_hypb[l * DD + lane + i * 32] = v[i];
}

__global__ void k_post_linear(int l) {
    int w = (blockIdx.x * blockDim.x + threadIdx.x) >> 5;
    int lane = threadIdx.x & 31;
    if (w >= NN) return;
    int o = w * DD + lane;
    float mv[4], hx[4], y[4];
#pragma unroll
    for (int i = 0; i < 4; i++) {
        int oo = o + i * 32;
        mv[i] = g_part[0][oo];
        hx[i] = g_h[oo];
        y[i] = g_hypb[l * DD + lane + i * 32];
    }
    float xn = rnorm4(hx);
    float mxn = rnorm4(mv);
    float s = tanhf(mxn / xn * artanhf_(xn)) / mxn;
#pragma unroll
    for (int i = 0; i < 4; i++) mv[i] *= s;
    proj4(mv);
    float x2 = wsum(mv[0] * mv[0] + mv[1] * mv[1] + mv[2] * mv[2] + mv[3] * mv[3]);
    float y2 = wsum(y[0] * y[0] + y[1] * y[1] + y[2] * y[2] + y[3] * y[3]);
    float xy = wsum(mv[0] * y[0] + mv[1] * y[1] + mv[2] * y[2] + mv[3] * y[3]);
    float ca = 1.0f + 2.0f * xy + y2;
    float cbf = 1.0f - x2;
    float den = fmaxf(1.0f + 2.0f * xy + x2 * y2, MINN);
#pragma unroll
    for (int i = 0; i < 4; i++) mv[i] = (ca * mv[i] + cbf * y[i]) / den;
    proj4(mv);
    logmap04(mv);
#pragma unroll
    for (int i = 0; i < 4; i++) g_log[o + i * 32] = mv[i];
}

__global__ void k_post_agg(int add_res, int save_res) {
    int w = (blockIdx.x * blockDim.x + threadIdx.x) >> 5;
    int lane = threadIdx.x & 31;
    if (w >= NN) return;
    int o = w * DD + lane;
    float v[4];
#pragma unroll
    for (int i = 0; i < 4; i++) {
        int oo = o + i * 32;
        v[i] = g_part[0][oo] + g_part[1][oo];
    }
    expmap04(v); proj4(v);
    logmap04(v);
#pragma unroll
    for (int i = 0; i < 4; i++) v[i] = fmaxf(v[i], 0.0f);
    expmap04(v); proj4(v);
    if (add_res) {
#pragma unroll
        for (int i = 0; i < 4; i++) v[i] += g_res[o + i * 32];
    }
#pragma unroll
    for (int i = 0; i < 4; i++) g_h[o + i * 32] = v[i];
    if (save_res) {
#pragma unroll
        for (int i = 0; i < 4; i++) g_res[o + i * 32] = v[i];
    }
}

__global__ void k_logmap() {
    int w = (blockIdx.x * blockDim.x + threadIdx.x) >> 5;
    int lane = threadIdx.x & 31;
    if (w >= NN) return;
    int o = w * DD + lane;
    float v[4];
#pragma unroll
    for (int i = 0; i < 4; i++) v[i] = g_h[o + i * 32];
    logmap04(v);
#pragma unroll
    for (int i = 0; i < 4; i++) g_log[o + i * 32] = v[i];
}

__global__ void k_zero() {
    if (threadIdx.x < NCENT) g_dsum[threadIdx.x] = 0.0f;
}

__global__ void k_cent(const float* __restrict__ cent) {
    __shared__ float sC[NCENT * 129];
    __shared__ float hs[4][DD];
    __shared__ float red[4][NCENT];
    int tx = threadIdx.x;
    int ty = threadIdx.y;
    int tid = ty * 64 + tx;
    for (int idx = tid; idx < NCENT * DD; idx += 256)
        sC[(idx >> 7) * 129 + (idx & 127)] = cent[idx];
    int n = (blockIdx.x << 2) + ty;
    const float* hr = g_h + (size_t)n * DD;
    hs[ty][tx] = hr[tx];
    hs[ty][tx + 64] = hr[tx + 64];
    __syncthreads();
    const float* cr = sC + tx * 129;
    float x2 = 0.f, xy = 0.f, y2 = 0.f;
#pragma unroll 4
    for (int k = 0; k < DD; k++) {
        float a = hs[ty][k];
        float b = cr[k];
        x2 += a * a; xy += a * b; y2 += b * b;
    }
    float A = 1.0f - 2.0f * xy + y2;
    float Bc = 1.0f - x2;
    float nn = 0.f;
#pragma unroll 4
    for (int k = 0; k < DD; k++) {
        float t = Bc * cr[k] - A * hs[ty][k];
        nn += t * t;
    }
    float den = fmaxf(1.0f - 2.0f * xy + x2 * y2, MINN);
    float d = fmaxf(sqrtf(nn) / den, MINN);
    red[ty][tx] = 2.0f * artanhf_(d);
    __syncthreads();
    if (ty == 0)
        atomicAdd(&g_dsum[tx], red[0][tx] + red[1][tx] + red[2][tx] + red[3][tx]);
}

__global__ void k_z(const float* __restrict__ W1, const float* __restrict__ b1) {
    int w = (blockIdx.x * blockDim.x + threadIdx.x) >> 5;
    int lane = threadIdx.x & 31;
    if (w >= NN) return;
    int o = w * DD + lane;
    float v[4];
#pragma unroll
    for (int i = 0; i < 4; i++) v[i] = g_log[o + i * 32];
#pragma unroll
    for (int cls = 0; cls < NCLS; cls++) {
        float p = 0.f;
#pragma unroll
        for (int i = 0; i < 4; i++) p += v[i] * W1[cls * DD + lane + i * 32];
        p = wsum(p);
        if (lane == 0) g_z[w * NCLS + cls] = p + b1[cls];
    }
}

__global__ void k_softmax(float* __restrict__ out) {
    int cls = blockIdx.x;
    int t = threadIdx.x;
    __shared__ float sh[256];
    float m = -1e30f;
    for (int n = t; n < NN; n += 256) m = fmaxf(m, g_z[n * NCLS + cls]);
    sh[t] = m; __syncthreads();
    for (int s = 128; s; s >>= 1) { if (t < s) sh[t] = fmaxf(sh[t], sh[t + s]); __syncthreads(); }
    m = sh[0]; __syncthreads();
    float ss = 0.f;
    for (int n = t; n < NN; n += 256) ss += expf(g_z[n * NCLS + cls] - m);
    sh[t] = ss; __syncthreads();
    for (int s = 128; s; s >>= 1) { if (t < s) sh[t] += sh[t + s]; __syncthreads(); }
    float inv = 1.0f / sh[0];
    for (int n = t; n < NN; n += 256)
        out[7 + n * NCLS + cls] = expf(g_z[n * NCLS + cls] - m) * inv;
}

__global__ void k_final(float* __restrict__ out, int hr_off) {
    int t = threadIdx.x;  // 64
    __shared__ float sh[64];
    float r = g_dsum[t] * (1.0f / (float)NN);
    sh[t] = r * r;
    __syncthreads();
    if (t == 0) {
        float s = 0.f;
        for (int i = 0; i < 64; i++) s += sh[i];
        sh[0] = s;
    }
    __syncthreads();
    float nrm = fmaxf(sqrtf(sh[0]), MINN);
    float s2 = artanhf_(nrm) / nrm;
    out[hr_off + t] = r * s2;
    if (t < NCLS) out[t] = 1.0f;
}

// ---------------- launch ----------------
extern "C" void kernel_launch(void* const* d_in, const int* in_sizes, int n_in,
                              void* d_out, int out_size) {
    const float* x = (const float*)d_in[0];
    const float* adj = (const float*)d_in[1];
    const float* W_conv = (const float*)d_in[3];
    const float* b_conv = (const float*)d_in[4];
    const float* cent = (const float*)d_in[5];
    const float* W1 = (const float*)d_in[8];
    const float* b1 = (const float*)d_in[9];
    float* out = (float*)d_out;

    float *p_h = 0, *p_logT = 0, *p_part = 0;
    cudaGetSymbolAddress((void**)&p_h, g_h);
    cudaGetSymbolAddress((void**)&p_logT, g_logT);
    cudaGetSymbolAddress((void**)&p_part, g_part);

    cudaFuncSetAttribute(k_tgemm, cudaFuncAttributeMaxDynamicSharedMemorySize, SMEMSZ);

    k_in<<<NN / 8, 256>>>(x);
    k_hypb<<<1, 128>>>(b_conv);

    for (int l = 0; l < NLAYER; l++) {
        // mobius matvec: h @ W^T
        k_tgemm<<<dim3(NN / BM, 1), 256, SMEMSZ>>>(
            p_h, W_conv + (size_t)l * DD * DD, DD, DD, DD / BK, p_part);
        k_post_linear<<<NN / 8, 256>>>(l);
        k_transpose<<<dim3(NN / 32, DD / 32), dim3(32, 8)>>>();
        // aggregation: adj @ logmap  (split-K = 2)
        k_tgemm<<<dim3(NN / BM, 2), 256, SMEMSZ>>>(
            adj, p_logT, NN, NN, NN / (2 * BK), p_part);
        int ar = (l == 1 || l == 3) ? 1 : 0;
        int sr = (l == 1) ? 1 : 0;
        k_post_agg<<<NN / 8, 256>>>(ar, sr);
    }
    k_logmap<<<NN / 8, 256>>>();
    k_zero<<<1, 64>>>();
    k_cent<<<NN / 4, dim3(64, 4)>>>(cent);
    k_z<<<NN / 8, 256>>>(W1, b1);
    k_softmax<<<NCLS, 256>>>(out);
    k_final<<<1, 64>>>(out, out_size - NCENT);
}

// round 4
// speedup vs baseline: 3.6279x; 1.6436x over previous
#include <cuda_runtime.h>
#include <math.h>
#include <stdint.h>

#define NN 8192
#define DD 128
#define NCENT 64
#define NCLS 7
#define NLAYER 4

#define MINN 1e-15f
#define EPSF 1e-5f
#define MAXNRM (1.0f - 1e-5f)

#define BM 128
#define BK 32
#define STAGE_BYTES 32768
#define SMEMSZ (3 * STAGE_BYTES)

// ---------------- scratch ----------------
static __device__ float g_adjr[(size_t)NN * NN];  // tf32-rounded adj
static __device__ float g_h[NN * DD];             // exact h
static __device__ float g_hr[NN * DD];            // tf32-rounded h (GEMM A)
static __device__ float g_res[NN * DD];
static __device__ float g_logT[DD * NN];          // transposed + rounded (GEMM B)
static __device__ float g_part[4][NN * DD];
static __device__ float g_hypb[NLAYER * DD];
static __device__ float g_Wr[NLAYER * DD * DD];   // rounded W
static __device__ float g_dsum[NCENT];
static __device__ float g_z[NN * NCLS];

// ---------------- helpers ----------------
__device__ __forceinline__ float wsum(float v) {
    v += __shfl_xor_sync(0xffffffffu, v, 16);
    v += __shfl_xor_sync(0xffffffffu, v, 8);
    v += __shfl_xor_sync(0xffffffffu, v, 4);
    v += __shfl_xor_sync(0xffffffffu, v, 2);
    v += __shfl_xor_sync(0xffffffffu, v, 1);
    return v;
}
__device__ __forceinline__ float artanhf_(float x) {
    x = fminf(fmaxf(x, -1.0f + EPSF), 1.0f - EPSF);
    return 0.5f * (log1pf(x) - log1pf(-x));
}
__device__ __forceinline__ float rnorm4(const float v[4]) {
    float s = v[0] * v[0] + v[1] * v[1] + v[2] * v[2] + v[3] * v[3];
    s = wsum(s);
    return fmaxf(sqrtf(s), MINN);
}
__device__ __forceinline__ void proj4(float v[4]) {
    float n = rnorm4(v);
    if (n > MAXNRM) {
        float s = MAXNRM / n;
        v[0] *= s; v[1] *= s; v[2] *= s; v[3] *= s;
    }
}
__device__ __forceinline__ void expmap04(float v[4]) {
    float n = rnorm4(v);
    float s = tanhf(n) / n;
    v[0] *= s; v[1] *= s; v[2] *= s; v[3] *= s;
}
__device__ __forceinline__ void logmap04(float v[4]) {
    float n = rnorm4(v);
    float s = artanhf_(n) / n;
    v[0] *= s; v[1] *= s; v[2] *= s; v[3] *= s;
}
__device__ __forceinline__ float rnaf(float x) {
    uint32_t r;
    asm("cvt.rna.tf32.f32 %0, %1;" : "=r"(r) : "f"(x));
    return __uint_as_float(r);
}
__device__ __forceinline__ uint32_t fu(float x) { return __float_as_uint(x); }

__device__ __forceinline__ void mma8(float c[4], uint32_t a0, uint32_t a1,
                                     uint32_t a2, uint32_t a3,
                                     uint32_t b0, uint32_t b1) {
    asm volatile(
        "mma.sync.aligned.m16n8k8.row.col.f32.tf32.tf32.f32 "
        "{%0,%1,%2,%3},{%4,%5,%6,%7},{%8,%9},{%0,%1,%2,%3};"
        : "+f"(c[0]), "+f"(c[1]), "+f"(c[2]), "+f"(c[3])
        : "r"(a0), "r"(a1), "r"(a2), "r"(a3), "r"(b0), "r"(b1));
}
__device__ __forceinline__ uint32_t smem_u32(const void* p) {
    uint32_t a;
    asm("{ .reg .u64 t; cvta.to.shared.u64 t, %1; cvt.u32.u64 %0, t; }" : "=r"(a) : "l"(p));
    return a;
}
__device__ __forceinline__ void cpa16(uint32_t dst, const float* src) {
    asm volatile("cp.async.cg.shared.global [%0], [%1], 16;" :: "r"(dst), "l"(src));
}
#define CPA_COMMIT() asm volatile("cp.async.commit_group;" ::: "memory")
#define CPA_WAIT1() asm volatile("cp.async.wait_group 1;" ::: "memory")

// ---------------- tf32 GEMM: 128 threads, BM=BN=128, BK=32, 3-stage cp.async
// C[m0..+127][0..127] = A @ Bt^T; A,Bt pre-rounded to tf32.
__global__ void __launch_bounds__(128, 2)
k_tgemm(const float* __restrict__ A, const float* __restrict__ Bt,
        int lda, int ldb, int iters, float* __restrict__ Cbase) {
    extern __shared__ float sm[];
    const uint32_t smb = smem_u32(sm);
    const int tid = threadIdx.x;
    const int m0 = blockIdx.x * BM;
    const long kbase = (long)blockIdx.y * iters * BK;
    float* Cout = Cbase + (size_t)blockIdx.y * NN * DD;

    // cp.async per-thread offsets: p in 0..7, idx = p*128+tid, r = idx>>3, cc = idx&7
    uint32_t dstOff[8], aG[8], bG[8];
#pragma unroll
    for (int p = 0; p < 8; p++) {
        int idx = p * 128 + tid;
        int r = idx >> 3, cc = idx & 7;
        dstOff[p] = (uint32_t)((r * 32 + ((cc ^ ((r & 1) << 2)) << 2)) << 2);
        aG[p] = (uint32_t)(r * lda + cc * 4);
        bG[p] = (uint32_t)(r * ldb + cc * 4);
    }
    const float* aBase = A + (size_t)m0 * lda + kbase;
    const float* bBase = Bt + kbase;

#define ISSUE(stage, it)                                                     \
    do {                                                                     \
        uint32_t _sA = smb + (uint32_t)(stage) * STAGE_BYTES;                \
        uint32_t _sB = _sA + 16384;                                          \
        const float* _ab = aBase + (size_t)(it) * BK;                        \
        const float* _bb = bBase + (size_t)(it) * BK;                        \
        _Pragma("unroll") for (int p = 0; p < 8; p++)                        \
            cpa16(_sA + dstOff[p], _ab + aG[p]);                             \
        _Pragma("unroll") for (int p = 0; p < 8; p++)                        \
            cpa16(_sB + dstOff[p], _bb + bG[p]);                             \
    } while (0)

    // compute-side precompute
    const int w = tid >> 5, lane = tid & 31;
    const int rr = lane >> 2, c = lane & 3;
    const int m0w = (w & 1) * 64, n0w = (w >> 1) * 64;
    uint32_t pc[2];
    pc[0] = (uint32_t)(((c) ^ ((rr & 1) << 2)) << 2);
    pc[1] = (uint32_t)(((c + 4) ^ ((rr & 1) << 2)) << 2);

    float acc[4][8][4];
#pragma unroll
    for (int mt = 0; mt < 4; mt++)
#pragma unroll
        for (int nt = 0; nt < 8; nt++)
#pragma unroll
            for (int e = 0; e < 4; e++) acc[mt][nt][e] = 0.0f;

    ISSUE(0, 0);
    CPA_COMMIT();
    ISSUE(1, 1);
    CPA_COMMIT();

    for (int i = 0; i < iters; i++) {
        CPA_WAIT1();
        __syncthreads();
        if (i + 2 < iters) ISSUE((i + 2) % 3, i + 2);
        CPA_COMMIT();

        const float* sA = sm + (size_t)(i % 3) * 8192;
        const float* sB = sA + 4096;
#pragma unroll
        for (int hb = 0; hb < 2; hb++) {
            float4 Af0[4], Af1[4];
#pragma unroll
            for (int mt = 0; mt < 4; mt++) {
                int base = (m0w + mt * 16 + rr) * 32 + pc[hb];
                Af0[mt] = *(const float4*)(sA + base);
                Af1[mt] = *(const float4*)(sA + base + 256);
            }
#pragma unroll
            for (int nt = 0; nt < 8; nt++) {
                float4 Bf = *(const float4*)(sB + (n0w + nt * 8 + rr) * 32 + pc[hb]);
#pragma unroll
                for (int mt = 0; mt < 4; mt++)
                    mma8(acc[mt][nt], fu(Af0[mt].x), fu(Af1[mt].x),
                         fu(Af0[mt].y), fu(Af1[mt].y), fu(Bf.x), fu(Bf.y));
#pragma unroll
                for (int mt = 0; mt < 4; mt++)
                    mma8(acc[mt][nt], fu(Af0[mt].z), fu(Af1[mt].z),
                         fu(Af0[mt].w), fu(Af1[mt].w), fu(Bf.z), fu(Bf.w));
            }
        }
    }
#undef ISSUE

    // epilogue
#pragma unroll
    for (int mt = 0; mt < 4; mt++) {
        int row = m0 + m0w + mt * 16 + rr;
#pragma unroll
        for (int nt = 0; nt < 8; nt++) {
            int col = n0w + nt * 8 + 2 * c;
            *(float2*)&Cout[(size_t)row * DD + col] =
                make_float2(acc[mt][nt][0], acc[mt][nt][1]);
            *(float2*)&Cout[(size_t)(row + 8) * DD + col] =
                make_float2(acc[mt][nt][2], acc[mt][nt][3]);
        }
    }
}

// ---------------- prep ----------------
__global__ void k_prep_adj(const float4* __restrict__ src, float4* __restrict__ dst) {
    size_t i = (size_t)blockIdx.x * 256 + threadIdx.x;
    const size_t total = (size_t)NN * NN / 4;
#pragma unroll
    for (int r = 0; r < 2; r++) {
        size_t idx = i + r * (total / 2);
        float4 v = src[idx];
        v.x = rnaf(v.x); v.y = rnaf(v.y); v.z = rnaf(v.z); v.w = rnaf(v.w);
        dst[idx] = v;
    }
}
__global__ void k_prepW(const float* __restrict__ W) {
    int i = blockIdx.x * 256 + threadIdx.x;  // 65536 total
    g_Wr[i] = rnaf(W[i]);
}

// ---------------- pointwise ----------------
__global__ void k_in(const float* __restrict__ x) {
    int w = (blockIdx.x * blockDim.x + threadIdx.x) >> 5;
    int lane = threadIdx.x & 31;
    if (w >= NN) return;
    const float* r = x + w * DD + lane;
    float v[4];
#pragma unroll
    for (int i = 0; i < 4; i++) v[i] = r[i * 32];
    expmap04(v);
    proj4(v);
    int o = w * DD + lane;
#pragma unroll
    for (int i = 0; i < 4; i++) {
        g_h[o + i * 32] = v[i];
        g_res[o + i * 32] = v[i];
        g_hr[o + i * 32] = rnaf(v[i]);
    }
}

__global__ void k_hypb(const float* __restrict__ b) {
    int l = threadIdx.x >> 5;
    int lane = threadIdx.x & 31;
    float v[4];
#pragma unroll
    for (int i = 0; i < 4; i++) v[i] = b[l * DD + lane + i * 32];
    expmap04(v);
    proj4(v);
#pragma unroll
    for (int i = 0; i < 4; i++) g_hypb[l * DD + lane + i * 32] = v[i];
}

// mobius scale + mobius_add(bias) + proj + logmap0, then transposed+rounded store
__global__ void k_post_linear_t(int l) {
    __shared__ float sT[32][129];
    int w = threadIdx.x >> 5, lane = threadIdx.x & 31;
    int n0 = blockIdx.x * 32;
    float y[4];
#pragma unroll
    for (int i = 0; i < 4; i++) y[i] = g_hypb[l * DD + lane + i * 32];
    float y2b = wsum(y[0] * y[0] + y[1] * y[1] + y[2] * y[2] + y[3] * y[3]);

    for (int s = 0; s < 4; s++) {
        int node = n0 + w * 4 + s;
        int o = node * DD + lane;
        float mv[4], hx[4];
#pragma unroll
        for (int i = 0; i < 4; i++) {
            mv[i] = g_part[0][o + i * 32];
            hx[i] = g_h[o + i * 32];
        }
        float xn = rnorm4(hx);
        float mxn = rnorm4(mv);
        float sc = tanhf(mxn / xn * artanhf_(xn)) / mxn;
#pragma unroll
        for (int i = 0; i < 4; i++) mv[i] *= sc;
        proj4(mv);
        float x2 = wsum(mv[0] * mv[0] + mv[1] * mv[1] + mv[2] * mv[2] + mv[3] * mv[3]);
        float xy = wsum(mv[0] * y[0] + mv[1] * y[1] + mv[2] * y[2] + mv[3] * y[3]);
        float ca = 1.0f + 2.0f * xy + y2b;
        float cbf = 1.0f - x2;
        float den = fmaxf(1.0f + 2.0f * xy + x2 * y2b, MINN);
#pragma unroll
        for (int i = 0; i < 4; i++) mv[i] = (ca * mv[i] + cbf * y[i]) / den;
        proj4(mv);
        logmap04(mv);
#pragma unroll
        for (int i = 0; i < 4; i++) sT[w * 4 + s][lane + i * 32] = mv[i];
    }
    __syncthreads();
    int d = threadIdx.x >> 1, nh = (threadIdx.x & 1) * 16;
    float* dst = &g_logT[(size_t)d * NN + n0 + nh];
#pragma unroll
    for (int j = 0; j < 16; j += 4) {
        float4 v = make_float4(rnaf(sT[nh + j][d]), rnaf(sT[nh + j + 1][d]),
                               rnaf(sT[nh + j + 2][d]), rnaf(sT[nh + j + 3][d]));
        *(float4*)(dst + j) = v;
    }
}

__global__ void k_post_agg(int add_res, int save_res) {
    int w = (blockIdx.x * blockDim.x + threadIdx.x) >> 5;
    int lane = threadIdx.x & 31;
    if (w >= NN) return;
    int o = w * DD + lane;
    float v[4];
#pragma unroll
    for (int i = 0; i < 4; i++) {
        int oo = o + i * 32;
        v[i] = (g_part[0][oo] + g_part[1][oo]) + (g_part[2][oo] + g_part[3][oo]);
    }
    expmap04(v); proj4(v);
    logmap04(v);
#pragma unroll
    for (int i = 0; i < 4; i++) v[i] = fmaxf(v[i], 0.0f);
    expmap04(v); proj4(v);
    if (add_res) {
#pragma unroll
        for (int i = 0; i < 4; i++) v[i] += g_res[o + i * 32];
    }
#pragma unroll
    for (int i = 0; i < 4; i++) {
        g_h[o + i * 32] = v[i];
        g_hr[o + i * 32] = rnaf(v[i]);
    }
    if (save_res) {
#pragma unroll
        for (int i = 0; i < 4; i++) g_res[o + i * 32] = v[i];
    }
}

__global__ void k_zero() {
    if (threadIdx.x < NCENT) g_dsum[threadIdx.x] = 0.0f;
}

__global__ void k_cent(const float* __restrict__ cent) {
    __shared__ float sC[NCENT * 129];
    __shared__ float hs[4][DD];
    __shared__ float red[4][NCENT];
    int tx = threadIdx.x, ty = threadIdx.y;
    int tid = ty * 64 + tx;
    for (int idx = tid; idx < NCENT * DD; idx += 256)
        sC[(idx >> 7) * 129 + (idx & 127)] = cent[idx];
    int n = (blockIdx.x << 2) + ty;
    const float* hr = g_h + (size_t)n * DD;
    hs[ty][tx] = hr[tx];
    hs[ty][tx + 64] = hr[tx + 64];
    __syncthreads();
    const float* cr = sC + tx * 129;
    float x2 = 0.f, xy = 0.f, y2 = 0.f;
#pragma unroll 4
    for (int k = 0; k < DD; k++) {
        float a = hs[ty][k];
        float b = cr[k];
        x2 += a * a; xy += a * b; y2 += b * b;
    }
    float A = 1.0f - 2.0f * xy + y2;
    float Bc = 1.0f - x2;
    float nn = 0.f;
#pragma unroll 4
    for (int k = 0; k < DD; k++) {
        float t = Bc * cr[k] - A * hs[ty][k];
        nn += t * t;
    }
    float den = fmaxf(1.0f - 2.0f * xy + x2 * y2, MINN);
    float d = fmaxf(sqrtf(nn) / den, MINN);
    red[ty][tx] = 2.0f * artanhf_(d);
    __syncthreads();
    if (ty == 0)
        atomicAdd(&g_dsum[tx], red[0][tx] + red[1][tx] + red[2][tx] + red[3][tx]);
}

// fused logmap0(h) + node-MLP logits
__global__ void k_z(const float* __restrict__ W1, const float* __restrict__ b1) {
    int w = (blockIdx.x * blockDim.x + threadIdx.x) >> 5;
    int lane = threadIdx.x & 31;
    if (w >= NN) return;
    int o = w * DD + lane;
    float v[4];
#pragma unroll
    for (int i = 0; i < 4; i++) v[i] = g_h[o + i * 32];
    logmap04(v);
#pragma unroll
    for (int cls = 0; cls < NCLS; cls++) {
        float p = 0.f;
#pragma unroll
        for (int i = 0; i < 4; i++) p += v[i] * W1[cls * DD + lane + i * 32];
        p = wsum(p);
        if (lane == 0) g_z[w * NCLS + cls] = p + b1[cls];
    }
}

__global__ void k_softmax(float* __restrict__ out) {
    int cls = blockIdx.x;
    int t = threadIdx.x;
    __shared__ float sh[256];
    float m = -1e30f;
    for (int n = t; n < NN; n += 256) m = fmaxf(m, g_z[n * NCLS + cls]);
    sh[t] = m; __syncthreads();
    for (int s = 128; s; s >>= 1) { if (t < s) sh[t] = fmaxf(sh[t], sh[t + s]); __syncthreads(); }
    m = sh[0]; __syncthreads();
    float ss = 0.f;
    for (int n = t; n < NN; n += 256) ss += expf(g_z[n * NCLS + cls] - m);
    sh[t] = ss; __syncthreads();
    for (int s = 128; s; s >>= 1) { if (t < s) sh[t] += sh[t + s]; __syncthreads(); }
    float inv = 1.0f / sh[0];
    for (int n = t; n < NN; n += 256)
        out[7 + n * NCLS + cls] = expf(g_z[n * NCLS + cls] - m) * inv;
}

__global__ void k_final(float* __restrict__ out, int hr_off) {
    int t = threadIdx.x;  // 64
    __shared__ float sh[64];
    float r = g_dsum[t] * (1.0f / (float)NN);
    sh[t] = r * r;
    __syncthreads();
    if (t == 0) {
        float s = 0.f;
        for (int i = 0; i < 64; i++) s += sh[i];
        sh[0] = s;
    }
    __syncthreads();
    float nrm = fmaxf(sqrtf(sh[0]), MINN);
    float s2 = artanhf_(nrm) / nrm;
    out[hr_off + t] = r * s2;
    if (t < NCLS) out[t] = 1.0f;
}

// ---------------- launch ----------------
extern "C" void kernel_launch(void* const* d_in, const int* in_sizes, int n_in,
                              void* d_out, int out_size) {
    const float* x = (const float*)d_in[0];
    const float* adj = (const float*)d_in[1];
    const float* W_conv = (const float*)d_in[3];
    const float* b_conv = (const float*)d_in[4];
    const float* cent = (const float*)d_in[5];
    const float* W1 = (const float*)d_in[8];
    const float* b1 = (const float*)d_in[9];
    float* out = (float*)d_out;

    float *p_adjr = 0, *p_hr = 0, *p_logT = 0, *p_Wr = 0, *p_part = 0;
    cudaGetSymbolAddress((void**)&p_adjr, g_adjr);
    cudaGetSymbolAddress((void**)&p_hr, g_hr);
    cudaGetSymbolAddress((void**)&p_logT, g_logT);
    cudaGetSymbolAddress((void**)&p_Wr, g_Wr);
    cudaGetSymbolAddress((void**)&p_part, g_part);

    cudaFuncSetAttribute(k_tgemm, cudaFuncAttributeMaxDynamicSharedMemorySize, SMEMSZ);

    k_prep_adj<<<32768, 256>>>((const float4*)adj, (float4*)p_adjr);
    k_in<<<NN / 8, 256>>>(x);
    k_hypb<<<1, 128>>>(b_conv);
    k_prepW<<<256, 256>>>(W_conv);

    for (int l = 0; l < NLAYER; l++) {
        // mobius matvec: h @ W^T  (iters = 128/32 = 4)
        k_tgemm<<<dim3(NN / BM, 1), 128, SMEMSZ>>>(
            p_hr, p_Wr + (size_t)l * DD * DD, DD, DD, DD / BK, p_part);
        k_post_linear_t<<<NN / 32, 256>>>(l);
        // aggregation: adj @ logmap, split-K = 4 (iters = 2048/32 = 64)
        k_tgemm<<<dim3(NN / BM, 4), 128, SMEMSZ>>>(
            p_adjr, p_logT, NN, NN, NN / (4 * BK), p_part);
        int ar = (l == 1 || l == 3) ? 1 : 0;
        int sr = (l == 1) ? 1 : 0;
        k_post_agg<<<NN / 8, 256>>>(ar, sr);
    }
    k_zero<<<1, 64>>>();
    k_cent<<<NN / 4, dim3(64, 4)>>>(cent);
    k_z<<<NN / 8, 256>>>(W1, b1);
    k_softmax<<<NCLS, 256>>>(out);
    k_final<<<1, 64>>>(out, out_size - NCENT);
}

// round 5
// speedup vs baseline: 3.8445x; 1.0597x over previous
#include <cuda_runtime.h>
#include <math.h>
#include <stdint.h>

#define NN 8192
#define DD 128
#define NCENT 64
#define NCLS 7
#define NLAYER 4

#define MINN 1e-15f
#define EPSF 1e-5f
#define MAXNRM (1.0f - 1e-5f)

#define BM 128
#define BK 32
#define STAGE_BYTES 32768
#define SMEMSZ (3 * STAGE_BYTES)

// ---------------- scratch ----------------
static __device__ float g_h[NN * DD];             // exact h (GEMM A, rounded in-reg)
static __device__ float g_res[NN * DD];
static __device__ float g_logT[DD * NN];          // transposed + rounded (GEMM B)
static __device__ float g_part[4][NN * DD];
static __device__ float g_hypb[NLAYER * DD];
static __device__ float g_Wr[NLAYER * DD * DD];   // rounded W (GEMM B)
static __device__ float g_dsum[NCENT];
static __device__ float g_z[NN * NCLS];

// ---------------- helpers ----------------
__device__ __forceinline__ float wsum(float v) {
    v += __shfl_xor_sync(0xffffffffu, v, 16);
    v += __shfl_xor_sync(0xffffffffu, v, 8);
    v += __shfl_xor_sync(0xffffffffu, v, 4);
    v += __shfl_xor_sync(0xffffffffu, v, 2);
    v += __shfl_xor_sync(0xffffffffu, v, 1);
    return v;
}
__device__ __forceinline__ float artanhf_(float x) {
    x = fminf(fmaxf(x, -1.0f + EPSF), 1.0f - EPSF);
    return 0.5f * (log1pf(x) - log1pf(-x));
}
__device__ __forceinline__ float rnorm4(const float v[4]) {
    float s = v[0] * v[0] + v[1] * v[1] + v[2] * v[2] + v[3] * v[3];
    s = wsum(s);
    return fmaxf(sqrtf(s), MINN);
}
__device__ __forceinline__ void proj4(float v[4]) {
    float n = rnorm4(v);
    if (n > MAXNRM) {
        float s = MAXNRM / n;
        v[0] *= s; v[1] *= s; v[2] *= s; v[3] *= s;
    }
}
__device__ __forceinline__ void expmap04(float v[4]) {
    float n = rnorm4(v);
    float s = tanhf(n) / n;
    v[0] *= s; v[1] *= s; v[2] *= s; v[3] *= s;
}
__device__ __forceinline__ void logmap04(float v[4]) {
    float n = rnorm4(v);
    float s = artanhf_(n) / n;
    v[0] *= s; v[1] *= s; v[2] *= s; v[3] *= s;
}
__device__ __forceinline__ float rnaf(float x) {
    uint32_t r;
    asm("cvt.rna.tf32.f32 %0, %1;" : "=r"(r) : "f"(x));
    return __uint_as_float(r);
}
__device__ __forceinline__ uint32_t rnau(float x) {
    uint32_t r;
    asm("cvt.rna.tf32.f32 %0, %1;" : "=r"(r) : "f"(x));
    return r;
}
__device__ __forceinline__ uint32_t fu(float x) { return __float_as_uint(x); }

__device__ __forceinline__ void mma8(float c[4], uint32_t a0, uint32_t a1,
                                     uint32_t a2, uint32_t a3,
                                     uint32_t b0, uint32_t b1) {
    asm volatile(
        "mma.sync.aligned.m16n8k8.row.col.f32.tf32.tf32.f32 "
        "{%0,%1,%2,%3},{%4,%5,%6,%7},{%8,%9},{%0,%1,%2,%3};"
        : "+f"(c[0]), "+f"(c[1]), "+f"(c[2]), "+f"(c[3])
        : "r"(a0), "r"(a1), "r"(a2), "r"(a3), "r"(b0), "r"(b1));
}
__device__ __forceinline__ uint32_t smem_u32(const void* p) {
    uint32_t a;
    asm("{ .reg .u64 t; cvta.to.shared.u64 t, %1; cvt.u32.u64 %0, t; }" : "=r"(a) : "l"(p));
    return a;
}
__device__ __forceinline__ void cpa16(uint32_t dst, const float* src) {
    asm volatile("cp.async.cg.shared.global [%0], [%1], 16;" :: "r"(dst), "l"(src));
}
#define CPA_COMMIT() asm volatile("cp.async.commit_group;" ::: "memory")
#define CPA_WAIT1() asm volatile("cp.async.wait_group 1;" ::: "memory")

// ---------------- tf32 GEMM: 128 threads, BM=BN=128, BK=32, 3-stage cp.async
// C[m0..+127][0..127] = A @ Bt^T; A raw fp32 (rna applied in-register after
// LDS), Bt pre-rounded to tf32.
__global__ void __launch_bounds__(128, 2)
k_tgemm(const float* __restrict__ A, const float* __restrict__ Bt,
        int lda, int ldb, int iters, float* __restrict__ Cbase) {
    extern __shared__ float sm[];
    const uint32_t smb = smem_u32(sm);
    const int tid = threadIdx.x;
    const int m0 = blockIdx.x * BM;
    const long kbase = (long)blockIdx.y * iters * BK;
    float* Cout = Cbase + (size_t)blockIdx.y * NN * DD;

    uint32_t dstOff[8], aG[8], bG[8];
#pragma unroll
    for (int p = 0; p < 8; p++) {
        int idx = p * 128 + tid;
        int r = idx >> 3, cc = idx & 7;
        dstOff[p] = (uint32_t)((r * 32 + ((cc ^ ((r & 1) << 2)) << 2)) << 2);
        aG[p] = (uint32_t)(r * lda + cc * 4);
        bG[p] = (uint32_t)(r * ldb + cc * 4);
    }
    const float* aBase = A + (size_t)m0 * lda + kbase;
    const float* bBase = Bt + kbase;

#define ISSUE(stage, it)                                                     \
    do {                                                                     \
        uint32_t _sA = smb + (uint32_t)(stage) * STAGE_BYTES;                \
        uint32_t _sB = _sA + 16384;                                          \
        const float* _ab = aBase + (size_t)(it) * BK;                        \
        const float* _bb = bBase + (size_t)(it) * BK;                        \
        _Pragma("unroll") for (int p = 0; p < 8; p++)                        \
            cpa16(_sA + dstOff[p], _ab + aG[p]);                             \
        _Pragma("unroll") for (int p = 0; p < 8; p++)                        \
            cpa16(_sB + dstOff[p], _bb + bG[p]);                             \
    } while (0)

    const int w = tid >> 5, lane = tid & 31;
    const int rr = lane >> 2, c = lane & 3;
    const int m0w = (w & 1) * 64, n0w = (w >> 1) * 64;
    uint32_t pc[2];
    pc[0] = (uint32_t)(((c) ^ ((rr & 1) << 2)) << 2);
    pc[1] = (uint32_t)(((c + 4) ^ ((rr & 1) << 2)) << 2);

    float acc[4][8][4];
#pragma unroll
    for (int mt = 0; mt < 4; mt++)
#pragma unroll
        for (int nt = 0; nt < 8; nt++)
#pragma unroll
            for (int e = 0; e < 4; e++) acc[mt][nt][e] = 0.0f;

    ISSUE(0, 0);
    CPA_COMMIT();
    ISSUE(1, 1);
    CPA_COMMIT();

    for (int i = 0; i < iters; i++) {
        CPA_WAIT1();
        __syncthreads();
        if (i + 2 < iters) ISSUE((i + 2) % 3, i + 2);
        CPA_COMMIT();

        const float* sA = sm + (size_t)(i % 3) * 8192;
        const float* sB = sA + 4096;
#pragma unroll
        for (int hb = 0; hb < 2; hb++) {
            uint32_t A0[4][4], A1[4][4];
#pragma unroll
            for (int mt = 0; mt < 4; mt++) {
                int base = (m0w + mt * 16 + rr) * 32 + pc[hb];
                float4 f0 = *(const float4*)(sA + base);
                float4 f1 = *(const float4*)(sA + base + 256);
                A0[mt][0] = rnau(f0.x); A0[mt][1] = rnau(f0.y);
                A0[mt][2] = rnau(f0.z); A0[mt][3] = rnau(f0.w);
                A1[mt][0] = rnau(f1.x); A1[mt][1] = rnau(f1.y);
                A1[mt][2] = rnau(f1.z); A1[mt][3] = rnau(f1.w);
            }
#pragma unroll
            for (int nt = 0; nt < 8; nt++) {
                float4 Bf = *(const float4*)(sB + (n0w + nt * 8 + rr) * 32 + pc[hb]);
#pragma unroll
                for (int mt = 0; mt < 4; mt++)
                    mma8(acc[mt][nt], A0[mt][0], A1[mt][0], A0[mt][1], A1[mt][1],
                         fu(Bf.x), fu(Bf.y));
#pragma unroll
                for (int mt = 0; mt < 4; mt++)
                    mma8(acc[mt][nt], A0[mt][2], A1[mt][2], A0[mt][3], A1[mt][3],
                         fu(Bf.z), fu(Bf.w));
            }
        }
    }
#undef ISSUE

#pragma unroll
    for (int mt = 0; mt < 4; mt++) {
        int row = m0 + m0w + mt * 16 + rr;
#pragma unroll
        for (int nt = 0; nt < 8; nt++) {
            int col = n0w + nt * 8 + 2 * c;
            *(float2*)&Cout[(size_t)row * DD + col] =
                make_float2(acc[mt][nt][0], acc[mt][nt][1]);
            *(float2*)&Cout[(size_t)(row + 8) * DD + col] =
                make_float2(acc[mt][nt][2], acc[mt][nt][3]);
        }
    }
}

// ---------------- prep ----------------
__global__ void k_prepW(const float* __restrict__ W) {
    int i = blockIdx.x * 256 + threadIdx.x;  // 65536 total
    g_Wr[i] = rnaf(W[i]);
}

// ---------------- pointwise ----------------
__global__ void k_in(const float* __restrict__ x) {
    int w = (blockIdx.x * blockDim.x + threadIdx.x) >> 5;
    int lane = threadIdx.x & 31;
    if (w >= NN) return;
    const float* r = x + w * DD + lane;
    float v[4];
#pragma unroll
    for (int i = 0; i < 4; i++) v[i] = r[i * 32];
    expmap04(v);
    proj4(v);
    int o = w * DD + lane;
#pragma unroll
    for (int i = 0; i < 4; i++) {
        g_h[o + i * 32] = v[i];
        g_res[o + i * 32] = v[i];
    }
}

__global__ void k_hypb(const float* __restrict__ b) {
    int l = threadIdx.x >> 5;
    int lane = threadIdx.x & 31;
    float v[4];
#pragma unroll
    for (int i = 0; i < 4; i++) v[i] = b[l * DD + lane + i * 32];
    expmap04(v);
    proj4(v);
#pragma unroll
    for (int i = 0; i < 4; i++) g_hypb[l * DD + lane + i * 32] = v[i];
}

// mobius scale + mobius_add(bias) + proj + logmap0, then transposed+rounded store
__global__ void k_post_linear_t(int l) {
    __shared__ float sT[32][129];
    int w = threadIdx.x >> 5, lane = threadIdx.x & 31;
    int n0 = blockIdx.x * 32;
    float y[4];
#pragma unroll
    for (int i = 0; i < 4; i++) y[i] = g_hypb[l * DD + lane + i * 32];
    float y2b = wsum(y[0] * y[0] + y[1] * y[1] + y[2] * y[2] + y[3] * y[3]);

    for (int s = 0; s < 4; s++) {
        int node = n0 + w * 4 + s;
        int o = node * DD + lane;
        float mv[4], hx[4];
#pragma unroll
        for (int i = 0; i < 4; i++) {
            mv[i] = g_part[0][o + i * 32];
            hx[i] = g_h[o + i * 32];
        }
        float xn = rnorm4(hx);
        float mxn = rnorm4(mv);
        float sc = tanhf(mxn / xn * artanhf_(xn)) / mxn;
#pragma unroll
        for (int i = 0; i < 4; i++) mv[i] *= sc;
        proj4(mv);
        float x2 = wsum(mv[0] * mv[0] + mv[1] * mv[1] + mv[2] * mv[2] + mv[3] * mv[3]);
        float xy = wsum(mv[0] * y[0] + mv[1] * y[1] + mv[2] * y[2] + mv[3] * y[3]);
        float ca = 1.0f + 2.0f * xy + y2b;
        float cbf = 1.0f - x2;
        float den = fmaxf(1.0f + 2.0f * xy + x2 * y2b, MINN);
#pragma unroll
        for (int i = 0; i < 4; i++) mv[i] = (ca * mv[i] + cbf * y[i]) / den;
        proj4(mv);
        logmap04(mv);
#pragma unroll
        for (int i = 0; i < 4; i++) sT[w * 4 + s][lane + i * 32] = mv[i];
    }
    __syncthreads();
    int d = threadIdx.x >> 1, nh = (threadIdx.x & 1) * 16;
    float* dst = &g_logT[(size_t)d * NN + n0 + nh];
#pragma unroll
    for (int j = 0; j < 16; j += 4) {
        float4 v = make_float4(rnaf(sT[nh + j][d]), rnaf(sT[nh + j + 1][d]),
                               rnaf(sT[nh + j + 2][d]), rnaf(sT[nh + j + 3][d]));
        *(float4*)(dst + j) = v;
    }
}

__global__ void k_post_agg(int add_res, int save_res) {
    int w = (blockIdx.x * blockDim.x + threadIdx.x) >> 5;
    int lane = threadIdx.x & 31;
    if (w >= NN) return;
    int o = w * DD + lane;
    float v[4];
#pragma unroll
    for (int i = 0; i < 4; i++) {
        int oo = o + i * 32;
        v[i] = (g_part[0][oo] + g_part[1][oo]) + (g_part[2][oo] + g_part[3][oo]);
    }
    expmap04(v); proj4(v);
    logmap04(v);
#pragma unroll
    for (int i = 0; i < 4; i++) v[i] = fmaxf(v[i], 0.0f);
    expmap04(v); proj4(v);
    if (add_res) {
#pragma unroll
        for (int i = 0; i < 4; i++) v[i] += g_res[o + i * 32];
    }
#pragma unroll
    for (int i = 0; i < 4; i++) g_h[o + i * 32] = v[i];
    if (save_res) {
#pragma unroll
        for (int i = 0; i < 4; i++) g_res[o + i * 32] = v[i];
    }
}

__global__ void k_zero() {
    if (threadIdx.x < NCENT) g_dsum[threadIdx.x] = 0.0f;
}

__global__ void k_cent(const float* __restrict__ cent) {
    __shared__ float sC[NCENT * 129];
    __shared__ float hs[4][DD];
    __shared__ float red[4][NCENT];
    int tx = threadIdx.x, ty = threadIdx.y;
    int tid = ty * 64 + tx;
    for (int idx = tid; idx < NCENT * DD; idx += 256)
        sC[(idx >> 7) * 129 + (idx & 127)] = cent[idx];
    int n = (blockIdx.x << 2) + ty;
    const float* hr = g_h + (size_t)n * DD;
    hs[ty][tx] = hr[tx];
    hs[ty][tx + 64] = hr[tx + 64];
    __syncthreads();
    const float* cr = sC + tx * 129;
    float x2 = 0.f, xy = 0.f, y2 = 0.f;
#pragma unroll 4
    for (int k = 0; k < DD; k++) {
        float a = hs[ty][k];
        float b = cr[k];
        x2 += a * a; xy += a * b; y2 += b * b;
    }
    float A = 1.0f - 2.0f * xy + y2;
    float Bc = 1.0f - x2;
    float nn = 0.f;
#pragma unroll 4
    for (int k = 0; k < DD; k++) {
        float t = Bc * cr[k] - A * hs[ty][k];
        nn += t * t;
    }
    float den = fmaxf(1.0f - 2.0f * xy + x2 * y2, MINN);
    float d = fmaxf(sqrtf(nn) / den, MINN);
    red[ty][tx] = 2.0f * artanhf_(d);
    __syncthreads();
    if (ty == 0)
        atomicAdd(&g_dsum[tx], red[0][tx] + red[1][tx] + red[2][tx] + red[3][tx]);
}

// fused logmap0(h) + node-MLP logits
__global__ void k_z(const float* __restrict__ W1, const float* __restrict__ b1) {
    int w = (blockIdx.x * blockDim.x + threadIdx.x) >> 5;
    int lane = threadIdx.x & 31;
    if (w >= NN) return;
    int o = w * DD + lane;
    float v[4];
#pragma unroll
    for (int i = 0; i < 4; i++) v[i] = g_h[o + i * 32];
    logmap04(v);
#pragma unroll
    for (int cls = 0; cls < NCLS; cls++) {
        float p = 0.f;
#pragma unroll
        for (int i = 0; i < 4; i++) p += v[i] * W1[cls * DD + lane + i * 32];
        p = wsum(p);
        if (lane == 0) g_z[w * NCLS + cls] = p + b1[cls];
    }
}

__global__ void k_softmax(float* __restrict__ out) {
    int cls = blockIdx.x;
    int t = threadIdx.x;
    __shared__ float sh[256];
    float m = -1e30f;
    for (int n = t; n < NN; n += 256) m = fmaxf(m, g_z[n * NCLS + cls]);
    sh[t] = m; __syncthreads();
    for (int s = 128; s; s >>= 1) { if (t < s) sh[t] = fmaxf(sh[t], sh[t + s]); __syncthreads(); }
    m = sh[0]; __syncthreads();
    float ss = 0.f;
    for (int n = t; n < NN; n += 256) ss += expf(g_z[n * NCLS + cls] - m);
    sh[t] = ss; __syncthreads();
    for (int s = 128; s; s >>= 1) { if (t < s) sh[t] += sh[t + s]; __syncthreads(); }
    float inv = 1.0f / sh[0];
    for (int n = t; n < NN; n += 256)
        out[7 + n * NCLS + cls] = expf(g_z[n * NCLS + cls] - m) * inv;
}

__global__ void k_final(float* __restrict__ out, int hr_off) {
    int t = threadIdx.x;  // 64
    __shared__ float sh[64];
    float r = g_dsum[t] * (1.0f / (float)NN);
    sh[t] = r * r;
    __syncthreads();
    if (t == 0) {
        float s = 0.f;
        for (int i = 0; i < 64; i++) s += sh[i];
        sh[0] = s;
    }
    __syncthreads();
    float nrm = fmaxf(sqrtf(sh[0]), MINN);
    float s2 = artanhf_(nrm) / nrm;
    out[hr_off + t] = r * s2;
    if (t < NCLS) out[t] = 1.0f;
}

// ---------------- launch ----------------
extern "C" void kernel_launch(void* const* d_in, const int* in_sizes, int n_in,
                              void* d_out, int out_size) {
    const float* x = (const float*)d_in[0];
    const float* adj = (const float*)d_in[1];
    const float* W_conv = (const float*)d_in[3];
    const float* b_conv = (const float*)d_in[4];
    const float* cent = (const float*)d_in[5];
    const float* W1 = (const float*)d_in[8];
    const float* b1 = (const float*)d_in[9];
    float* out = (float*)d_out;

    float *p_h = 0, *p_logT = 0, *p_Wr = 0, *p_part = 0;
    cudaGetSymbolAddress((void**)&p_h, g_h);
    cudaGetSymbolAddress((void**)&p_logT, g_logT);
    cudaGetSymbolAddress((void**)&p_Wr, g_Wr);
    cudaGetSymbolAddress((void**)&p_part, g_part);

    cudaFuncSetAttribute(k_tgemm, cudaFuncAttributeMaxDynamicSharedMemorySize, SMEMSZ);

    k_in<<<NN / 8, 256>>>(x);
    k_hypb<<<1, 128>>>(b_conv);
    k_prepW<<<256, 256>>>(W_conv);

    for (int l = 0; l < NLAYER; l++) {
        // mobius matvec: h @ W^T  (iters = 128/32 = 4)
        k_tgemm<<<dim3(NN / BM, 1), 128, SMEMSZ>>>(
            p_h, p_Wr + (size_t)l * DD * DD, DD, DD, DD / BK, p_part);
        k_post_linear_t<<<NN / 32, 256>>>(l);
        // aggregation: adj @ logmap, split-K = 4 (iters = 2048/32 = 64)
        k_tgemm<<<dim3(NN / BM, 4), 128, SMEMSZ>>>(
            adj, p_logT, NN, NN, NN / (4 * BK), p_part);
        int ar = (l == 1 || l == 3) ? 1 : 0;
        int sr = (l == 1) ? 1 : 0;
        k_post_agg<<<NN / 8, 256>>>(ar, sr);
    }
    k_zero<<<1, 64>>>();
    k_cent<<<NN / 4, dim3(64, 4)>>>(cent);
    k_z<<<NN / 8, 256>>>(W1, b1);
    k_softmax<<<NCLS, 256>>>(out);
    k_final<<<1, 64>>>(out, out_size - NCENT);
}